// round 11
// baseline (speedup 1.0000x reference)
#include <cuda_runtime.h>

// Problem constants (fixed by reference)
#define BATCH   1000
#define NUE_    4
#define K_      500
#define M_      500
#define N_      1000
#define NSYM_   250
#define NEDGE_  2000
#define NINFOE_ 1500
#define NITER_  5

// Static scratch
__device__ float g_llr[BATCH * NUE_ * N_];   // channel LLRs
__device__ short g_eoff[M_ + 1];
__device__ short g_elist[NINFOE_];
__device__ short g_perm[M_];                 // checks sorted by degree

// ---------------------------------------------------------------------------
// Hybrid tanh (validated R3-R10) — init only.
// ---------------------------------------------------------------------------
__device__ __forceinline__ float tanh_clip_half(float x) {
    x = fminf(fmaxf(x, -9.9f), 9.9f);
    float ax = fabsf(x);
    float x2 = x * x;
    float num = x * fmaf(x2, fmaf(x2, 1.0f, 105.0f), 945.0f);
    float den = fmaf(x2, fmaf(x2, 15.0f, 420.0f), 945.0f);
    float tp  = __fdividef(num, den);
    float e   = __expf(2.0f * ax);
    float te  = copysignf(1.0f - __fdividef(2.0f, e + 1.0f), x);
    float t   = (ax < 1.0f) ? tp : te;
    return (t >= 0.f) ? fmaxf(t, 1e-7f) : fminf(t, -1e-7f);
}

__device__ __forceinline__ float clip999(float x) {
    return fminf(fmaxf(x, -0.999999f), 0.999999f);
}

__device__ __forceinline__ float msg_floor(float t) {
    return (t >= 0.f) ? fmaxf(t, 1e-7f) : fminf(t, -1e-7f);
}

// Variable update, one lane: previous messages m0..m2, check products p0..p2,
// el = clamped exp(Lch). Emits the three new messages.
// rho_i = clip(p_i / m_i) via one reciprocal; message_i = tanh((vt-c_i)/2)
// = (A_i - B_i)/(A_i + B_i), A_i = el*np_j*np_k, B_i = nm_j*nm_k.
__device__ __forceinline__ void var_update(float m0, float m1, float m2,
                                           float p0, float p1, float p2,
                                           float el,
                                           float& o0, float& o1, float& o2) {
    float inv = __fdividef(1.0f, m0 * m1 * m2);
    float r0 = clip999(p0 * (m1 * m2) * inv);
    float r1 = clip999(p1 * (m0 * m2) * inv);
    float r2 = clip999(p2 * (m0 * m1) * inv);
    float np0 = 1.0f + r0, nm0 = 1.0f - r0;
    float np1 = 1.0f + r1, nm1 = 1.0f - r1;
    float np2 = 1.0f + r2, nm2 = 1.0f - r2;
    float e0 = el * np0;
    float A0 = el * (np1 * np2), A1 = e0 * np2, A2 = e0 * np1;
    float B0 = nm1 * nm2,        B1 = nm0 * nm2, B2 = nm0 * nm1;
    o0 = msg_floor(__fdividef(A0 - B0, A0 + B0));
    o1 = msg_floor(__fdividef(A1 - B1, A1 + B1));
    o2 = msg_floor(__fdividef(A2 - B2, A2 + B2));
}

// Final decision, one lane: bit = (e^{vtot} < 1) <=> el*Prod(np) < Prod(nm)
__device__ __forceinline__ float var_decide(float m0, float m1, float m2,
                                            float p0, float p1, float p2,
                                            float el) {
    float inv = __fdividef(1.0f, m0 * m1 * m2);
    float r0 = clip999(p0 * (m1 * m2) * inv);
    float r1 = clip999(p1 * (m0 * m2) * inv);
    float r2 = clip999(p2 * (m0 * m1) * inv);
    float U = el * ((1.0f + r0) * (1.0f + r1)) * (1.0f + r2);
    float D = ((1.0f - r0) * (1.0f - r1)) * (1.0f - r2);
    return (U < D) ? 1.0f : 0.0f;
}

// ---------------------------------------------------------------------------
// Fused encode + LMMSE. Block 0 additionally builds the check-node CSR and
// the degree-sorted check permutation (consumed only by decode) — hidden in
// the wave structure. Parity via shared atomicXor over the raw cn edge list.
// ---------------------------------------------------------------------------
__global__ __launch_bounds__(256)
void enc_lmmse_kernel(const int* __restrict__ bin,
                      const int* __restrict__ cn,
                      const float4* __restrict__ hre4, const float4* __restrict__ him4,
                      const float4* __restrict__ nre4, const float4* __restrict__ nim4,
                      const float* __restrict__ ebno,
                      float* __restrict__ out_bf)
{
    __shared__ char scratch[12032];
    unsigned char* bits = (unsigned char*)scratch;      // [NUE_*N_] = 4000
    int* sp = (int*)(scratch + 4000);                   // [NUE_*M_] = 8000

    const int b = blockIdx.x;
    const int t = threadIdx.x;
    const int lane = t & 31, wid = t >> 5;

    // ---- block 0 only: build CSR + degree-sorted perm ----
    if (b == 0) {
        int*   cnt  = (int*)scratch;            // [M_]   2000
        int*   base = (int*)(scratch + 2000);   // [M_]   2000
        int*   wsum = (int*)(scratch + 4000);   // [8]      32
        short* sel  = (short*)(scratch + 4032); // [NINFOE_] 3000

        for (int m = t; m < M_; m += 256) cnt[m] = 0;
        __syncthreads();
        for (int e = t; e < NINFOE_; e += 256) atomicAdd(&cnt[cn[e]], 1);
        __syncthreads();
        int v0 = (2 * t     < M_) ? cnt[2 * t]     : 0;
        int v1 = (2 * t + 1 < M_) ? cnt[2 * t + 1] : 0;
        int s = v0 + v1, x = s;
#pragma unroll
        for (int d = 1; d < 32; d <<= 1) {
            int nn = __shfl_up_sync(0xffffffffu, x, d);
            if (lane >= d) x += nn;
        }
        if (lane == 31) wsum[wid] = x;
        __syncthreads();
        if (wid == 0) {
            int s2 = (lane < 8) ? wsum[lane] : 0;
#pragma unroll
            for (int d = 1; d < 8; d <<= 1) {
                int nn = __shfl_up_sync(0xffffffffu, s2, d);
                if (lane >= d) s2 += nn;
            }
            if (lane < 8) wsum[lane] = s2;
        }
        __syncthreads();
        int ex = x + ((wid > 0) ? wsum[wid - 1] : 0) - s;
        if (2 * t     < M_) { base[2 * t]     = ex;      g_eoff[2 * t]     = (short)ex; }
        if (2 * t + 1 < M_) { base[2 * t + 1] = ex + v0; g_eoff[2 * t + 1] = (short)(ex + v0); }
        if (t == 0) g_eoff[M_] = (short)NINFOE_;
        __syncthreads();
        for (int m = t; m < M_; m += 256) cnt[m] = 0;
        __syncthreads();
        for (int e = t; e < NINFOE_; e += 256) {
            int c = cn[e];
            int sl = atomicAdd(&cnt[c], 1);
            sel[base[c] + sl] = (short)e;
        }
        __syncthreads();
        for (int m = t; m < M_; m += 256) {
            int o0 = base[m], o1 = o0 + cnt[m];
            for (int i = o0 + 1; i < o1; i++) {
                short vv = sel[i];
                int j = i - 1;
                while (j >= o0 && sel[j] > vv) { sel[j + 1] = sel[j]; j--; }
                sel[j + 1] = vv;
            }
        }
        __syncthreads();
        for (int e = t; e < NINFOE_; e += 256) g_elist[e] = sel[e];
        __syncthreads();

        // degree-sorted permutation of checks (counting sort, degrees 0..31)
        int* dh  = (int*)scratch;           // [32]
        int* dhb = (int*)scratch + 32;      // [32]
        if (t < 32) dh[t] = 0;
        __syncthreads();
        for (int m = t; m < M_; m += 256) {
            int d = min((int)(g_eoff[m + 1] - g_eoff[m]), 31);
            atomicAdd(&dh[d], 1);
        }
        __syncthreads();
        if (t == 0) {
            int run = 0;
            for (int d = 0; d < 32; d++) { dhb[d] = run; run += dh[d]; }
        }
        __syncthreads();
        for (int m = t; m < M_; m += 256) {
            int d = min((int)(g_eoff[m + 1] - g_eoff[m]), 31);
            int sl = atomicAdd(&dhb[d], 1);
            g_perm[sl] = (short)m;
        }
        __syncthreads();
    }

    // ---- stage info bits, emit bf output, zero parity accumulators ----
    const int* bb = bin + (size_t)b * NUE_ * K_;
    float* of = out_bf + (size_t)b * NUE_ * K_;
    for (int i = t; i < NUE_ * K_; i += 256) {
        int ue = i / K_, n = i - ue * K_;
        int bit = bb[i];
        bits[ue * N_ + n] = (unsigned char)bit;
        of[i] = (float)bit;
    }
    for (int i = t; i < NUE_ * M_; i += 256) sp[i] = 0;
    __syncthreads();

    // ---- parity via atomicXor over info edges (vn[e] = e/3 analytically) ----
    for (int e = t; e < NINFOE_; e += 256) {
        int c = cn[e], v = e / 3;
#pragma unroll
        for (int ue = 0; ue < 4; ue++)
            if (bits[ue * N_ + v]) atomicXor(&sp[ue * M_ + c], 1);
    }
    __syncthreads();
    for (int i = t; i < NUE_ * M_; i += 256) {
        int ue = i / M_, m = i - ue * M_;
        bits[ue * N_ + K_ + m] = (unsigned char)sp[i];
    }
    __syncthreads();

    if (t >= NSYM_) return;

    const float no  = 1.0f / (exp10f(ebno[0] * 0.1f) * 2.0f);
    const int r = b * NSYM_ + t;
    const float is2 = 0.70710678118654752440f;
    const float s10 = 0.31622776601683794f;

    float hr[4][4], hi[4][4];
#pragma unroll
    for (int i = 0; i < 4; i++) {
        float4 vr = hre4[r * 4 + i];
        float4 vi = him4[r * 4 + i];
        hr[i][0] = vr.x * is2; hr[i][1] = vr.y * is2; hr[i][2] = vr.z * is2; hr[i][3] = vr.w * is2;
        hi[i][0] = vi.x * is2; hi[i][1] = vi.y * is2; hi[i][2] = vi.z * is2; hi[i][3] = vi.w * is2;
    }

    float xr[4], xi[4];
#pragma unroll
    for (int j = 0; j < 4; j++) {
        uchar4 cb = *(const uchar4*)&bits[j * N_ + 4 * t];
        xr[j] = (float)((1 - 2 * (int)cb.x) * (1 + 2 * (int)cb.z)) * s10;
        xi[j] = (float)((1 - 2 * (int)cb.y) * (1 + 2 * (int)cb.w)) * s10;
    }

    const float ns = sqrtf(no * 0.5f);
    float4 wr4 = nre4[r], wi4 = nim4[r];
    float yr[4] = {wr4.x * ns, wr4.y * ns, wr4.z * ns, wr4.w * ns};
    float yi[4] = {wi4.x * ns, wi4.y * ns, wi4.z * ns, wi4.w * ns};
#pragma unroll
    for (int i = 0; i < 4; i++)
#pragma unroll
        for (int j = 0; j < 4; j++) {
            yr[i] += hr[i][j] * xr[j] - hi[i][j] * xi[j];
            yi[i] += hr[i][j] * xi[j] + hi[i][j] * xr[j];
        }

    float rr[4], ri[4];
#pragma unroll
    for (int j = 0; j < 4; j++) {
        float ar = 0.f, ai = 0.f;
#pragma unroll
        for (int i = 0; i < 4; i++) {
            ar += hr[i][j] * yr[i] + hi[i][j] * yi[i];
            ai += hr[i][j] * yi[i] - hi[i][j] * yr[i];
        }
        rr[j] = ar; ri[j] = ai;
    }

    float Br[4][4], Bi[4][4];
#pragma unroll
    for (int j = 0; j < 4; j++)
#pragma unroll
        for (int k = 0; k < 4; k++) {
            if (k > j) continue;
            float ar = (j == k) ? no : 0.f;
            float ai = 0.f;
#pragma unroll
            for (int i = 0; i < 4; i++) {
                ar += hr[i][j] * hr[i][k] + hi[i][j] * hi[i][k];
                ai += hr[i][j] * hi[i][k] - hi[i][j] * hr[i][k];
            }
            Br[j][k] = ar; Bi[j][k] = ai;
        }

    float rk[4];
#pragma unroll
    for (int k = 0; k < 4; k++) {
        float v = Br[k][k];
#pragma unroll
        for (int j = 0; j < 4; j++)
            if (j < k) v -= Br[k][j] * Br[k][j] + Bi[k][j] * Bi[k][j];
        float inv = rsqrtf(v);
        rk[k] = inv;
#pragma unroll
        for (int i = 0; i < 4; i++) {
            if (i <= k) continue;
            float cr = Br[i][k], ci = Bi[i][k];
#pragma unroll
            for (int j = 0; j < 4; j++)
                if (j < k) {
                    cr -= Br[i][j] * Br[k][j] + Bi[i][j] * Bi[k][j];
                    ci -= Bi[i][j] * Br[k][j] - Br[i][j] * Bi[k][j];
                }
            Br[i][k] = cr * inv; Bi[i][k] = ci * inv;
        }
    }

    float vr_[4], vi_[4];
#pragma unroll
    for (int i = 0; i < 4; i++) {
        float ar = rr[i], ai = ri[i];
#pragma unroll
        for (int j = 0; j < 4; j++)
            if (j < i) {
                ar -= Br[i][j] * vr_[j] - Bi[i][j] * vi_[j];
                ai -= Br[i][j] * vi_[j] + Bi[i][j] * vr_[j];
            }
        vr_[i] = ar * rk[i]; vi_[i] = ai * rk[i];
    }
    float xrw[4], xiw[4];
#pragma unroll
    for (int ii = 0; ii < 4; ii++) {
        int i = 3 - ii;
        float ar = vr_[i], ai = vi_[i];
#pragma unroll
        for (int j = 0; j < 4; j++)
            if (j > i) {
                ar -= Br[j][i] * xrw[j] + Bi[j][i] * xiw[j];
                ai -= Br[j][i] * xiw[j] - Bi[j][i] * xrw[j];
            }
        xrw[i] = ar * rk[i]; xiw[i] = ai * rk[i];
    }

    float dj[4];
#pragma unroll
    for (int j = 0; j < 4; j++) {
        float wr[4], wi[4];
#pragma unroll
        for (int i = 0; i < 4; i++) { wr[i] = 0.f; wi[i] = 0.f; }
        wr[j] = rk[j];
        float acc = rk[j] * rk[j];
#pragma unroll
        for (int i = 0; i < 4; i++) {
            if (i <= j) continue;
            float sr = 0.f, si = 0.f;
#pragma unroll
            for (int q = 0; q < 4; q++)
                if (q >= j && q < i) {
                    sr += Br[i][q] * wr[q] - Bi[i][q] * wi[q];
                    si += Br[i][q] * wi[q] + Bi[i][q] * wr[q];
                }
            wr[i] = -sr * rk[i]; wi[i] = -si * rk[i];
            acc += wr[i] * wr[i] + wi[i] * wi[i];
        }
        dj[j] = acc;
    }

#pragma unroll
    for (int c = 0; c < 4; c++) {
        float d = 1.0f - no * dj[c];
        float invd = 1.0f / d;
        float xhr = xrw[c] * invd, xhi = xiw[c] * invd;
        float noeff = fmaxf(invd - 1.0f, 1e-12f);
        float inoe = 1.0f / noeff;

        float a1  = xhr - s10,  a3  = xhr - 3.f * s10;
        float am1 = xhr + s10,  am3 = xhr + 3.f * s10;
        float f1 = -(a1 * a1), f3 = -(a3 * a3), fm1 = -(am1 * am1), fm3 = -(am3 * am3);
        float g1_ = xhi - s10,  g3_ = xhi - 3.f * s10;
        float gm1_ = xhi + s10, gm3_ = xhi + 3.f * s10;
        float g1 = -(g1_ * g1_), g3 = -(g3_ * g3_), gm1 = -(gm1_ * gm1_), gm3 = -(gm3_ * gm3_);

        float4 out = make_float4((fmaxf(f1, f3)  - fmaxf(fm1, fm3)) * inoe,
                                 (fmaxf(g1, g3)  - fmaxf(gm1, gm3)) * inoe,
                                 (fmaxf(f1, fm1) - fmaxf(f3, fm3))  * inoe,
                                 (fmaxf(g1, gm1) - fmaxf(g3, gm3))  * inoe);
        *(float4*)&g_llr[(size_t)(b * NUE_ + c) * N_ + 4 * t] = out;
    }
}

// ---------------------------------------------------------------------------
// Decoder: one block per batch element, 4 codewords as float4 lanes, 512 thr.
// Check threads handle degree-sorted checks (g_perm) to kill warp divergence.
// Variable phase: 4 MUFU per lane (1 reciprocal for rhos + 3 message divs),
// exponential-domain messages; final decision div-free.
// ---------------------------------------------------------------------------
extern __shared__ unsigned char dynsmem[];
#define DEC_SMEM (24000 + 8000 + 8000 + 8000 + 3000)

__global__ __launch_bounds__(512, 4)
void decode_kernel(const int* __restrict__ cn, float* __restrict__ out_bhat) {
    float4* sT  = (float4*)dynsmem;          // [NINFOE_] v->c message tanh
    float4* sP  = sT + NINFOE_;              // [M_]  check products
    float4* sTp = sP + M_;                   // [M_]  parity-edge tanh (invariant)
    float4* sEL = sTp + M_;                  // [K_]  clamped exp(Lch)
    short* selist = (short*)(sEL + K_);      // [NINFOE_]

    const int b = blockIdx.x;
    const int t = threadIdx.x;
    const float* Lb = g_llr + (size_t)b * NUE_ * N_;

    for (int e = t; e < NINFOE_; e += 512) selist[e] = g_elist[e];

    int c0 = 0, c1 = 0, c2 = 0, mc = 0, co0 = 0, co1 = 0;
    if (t < K_) {
        float4 l;
        l.x = Lb[0 * N_ + t]; l.y = Lb[1 * N_ + t];
        l.z = Lb[2 * N_ + t]; l.w = Lb[3 * N_ + t];
        float4 el;
        el.x = fminf(__expf(l.x), 1e30f); el.y = fminf(__expf(l.y), 1e30f);
        el.z = fminf(__expf(l.z), 1e30f); el.w = fminf(__expf(l.w), 1e30f);
        sEL[t] = el;
        c0 = cn[3 * t]; c1 = cn[3 * t + 1]; c2 = cn[3 * t + 2];
        float4 m;
        m.x = tanh_clip_half(l.x * 0.5f);
        m.y = tanh_clip_half(l.y * 0.5f);
        m.z = tanh_clip_half(l.z * 0.5f);
        m.w = tanh_clip_half(l.w * 0.5f);
        sT[3 * t] = m; sT[3 * t + 1] = m; sT[3 * t + 2] = m;
    }
    if (t < M_) {
        float4 lp;
        lp.x = Lb[0 * N_ + K_ + t]; lp.y = Lb[1 * N_ + K_ + t];
        lp.z = Lb[2 * N_ + K_ + t]; lp.w = Lb[3 * N_ + K_ + t];
        float4 tp;
        tp.x = tanh_clip_half(lp.x * 0.5f);
        tp.y = tanh_clip_half(lp.y * 0.5f);
        tp.z = tanh_clip_half(lp.z * 0.5f);
        tp.w = tanh_clip_half(lp.w * 0.5f);
        sTp[t] = tp;
        mc = g_perm[t];
        co0 = g_eoff[mc]; co1 = g_eoff[mc + 1];
    }
    __syncthreads();

    float* oh = out_bhat + (size_t)b * NUE_ * K_;

    for (int it = 0; it < NITER_; it++) {
        // check phase: product over info edges * parity tanh -> sP[mc]
        if (t < M_) {
            float4 p = sTp[mc];
            for (int q = co0; q < co1; q++) {
                float4 tt = sT[selist[q]];
                p.x *= tt.x; p.y *= tt.y; p.z *= tt.z; p.w *= tt.w;
            }
            sP[mc] = p;
        }
        __syncthreads();
        // variable phase
        if (t < K_) {
            float4 m0 = sT[3 * t], m1 = sT[3 * t + 1], m2 = sT[3 * t + 2];
            float4 p0 = sP[c0], p1 = sP[c1], p2 = sP[c2];
            float4 el = sEL[t];
            if (it < NITER_ - 1) {
                float4 o0, o1, o2;
                var_update(m0.x, m1.x, m2.x, p0.x, p1.x, p2.x, el.x, o0.x, o1.x, o2.x);
                var_update(m0.y, m1.y, m2.y, p0.y, p1.y, p2.y, el.y, o0.y, o1.y, o2.y);
                var_update(m0.z, m1.z, m2.z, p0.z, p1.z, p2.z, el.z, o0.z, o1.z, o2.z);
                var_update(m0.w, m1.w, m2.w, p0.w, p1.w, p2.w, el.w, o0.w, o1.w, o2.w);
                sT[3 * t] = o0; sT[3 * t + 1] = o1; sT[3 * t + 2] = o2;
            } else {
                oh[0 * K_ + t] = var_decide(m0.x, m1.x, m2.x, p0.x, p1.x, p2.x, el.x);
                oh[1 * K_ + t] = var_decide(m0.y, m1.y, m2.y, p0.y, p1.y, p2.y, el.y);
                oh[2 * K_ + t] = var_decide(m0.z, m1.z, m2.z, p0.z, p1.z, p2.z, el.z);
                oh[3 * K_ + t] = var_decide(m0.w, m1.w, m2.w, p0.w, p1.w, p2.w, el.w);
            }
        }
        if (it < NITER_ - 1) __syncthreads();
    }
}

// ---------------------------------------------------------------------------
extern "C" void kernel_launch(void* const* d_in, const int* in_sizes, int n_in,
                              void* d_out, int out_size) {
    int shift = 10 - n_in;
    const float* ebno = (const float*)d_in[1 - shift];
    const int*   b    = (const int*)  d_in[2 - shift];
    const int*   cn   = (const int*)  d_in[4 - shift];
    const float* h_re = (const float*)d_in[6 - shift];
    const float* h_im = (const float*)d_in[7 - shift];
    const float* n_re = (const float*)d_in[8 - shift];
    const float* n_im = (const float*)d_in[9 - shift];

    float* out_bf = (float*)d_out;                       // (batch, NUE, K)
    float* out_bh = (float*)d_out + BATCH * NUE_ * K_;   // (batch, NUE, K)

    cudaFuncSetAttribute(decode_kernel, cudaFuncAttributeMaxDynamicSharedMemorySize, DEC_SMEM);

    enc_lmmse_kernel<<<BATCH, 256>>>(b, cn,
                                     (const float4*)h_re, (const float4*)h_im,
                                     (const float4*)n_re, (const float4*)n_im,
                                     ebno, out_bf);
    decode_kernel<<<BATCH, 512, DEC_SMEM>>>(cn, out_bh);
}

// round 12
// speedup vs baseline: 1.0031x; 1.0031x over previous
#include <cuda_runtime.h>

// Problem constants (fixed by reference)
#define BATCH   1000
#define NUE_    4
#define K_      500
#define M_      500
#define N_      1000
#define NSYM_   250
#define NEDGE_  2000
#define NINFOE_ 1500
#define NITER_  5

// Static scratch
__device__ float g_llr[BATCH * NUE_ * N_];   // channel LLRs
__device__ short g_eoff[M_ + 1];
__device__ short g_elist[NINFOE_];

// ---------------------------------------------------------------------------
// Hybrid tanh (validated R3-R11) — init only.
// ---------------------------------------------------------------------------
__device__ __forceinline__ float tanh_clip_half(float x) {
    x = fminf(fmaxf(x, -9.9f), 9.9f);
    float ax = fabsf(x);
    float x2 = x * x;
    float num = x * fmaf(x2, fmaf(x2, 1.0f, 105.0f), 945.0f);
    float den = fmaf(x2, fmaf(x2, 15.0f, 420.0f), 945.0f);
    float tp  = __fdividef(num, den);
    float e   = __expf(2.0f * ax);
    float te  = copysignf(1.0f - __fdividef(2.0f, e + 1.0f), x);
    float t   = (ax < 1.0f) ? tp : te;
    return (t >= 0.f) ? fmaxf(t, 1e-7f) : fminf(t, -1e-7f);
}

__device__ __forceinline__ float clip999(float x) {
    return fminf(fmaxf(x, -0.999999f), 0.999999f);
}

__device__ __forceinline__ float msg_floor(float t) {
    return (t >= 0.f) ? fmaxf(t, 1e-7f) : fminf(t, -1e-7f);
}

// Variable update, one lane (validated R11: rel_err 0.0).
// rho_i = clip(p_i/m_i) via one reciprocal; message_i = (A_i-B_i)/(A_i+B_i),
// A_i = el*np_j*np_k, B_i = nm_j*nm_k  (exponential-domain tanh identity).
__device__ __forceinline__ void var_update(float m0, float m1, float m2,
                                           float p0, float p1, float p2,
                                           float el,
                                           float& o0, float& o1, float& o2) {
    float inv = __fdividef(1.0f, m0 * m1 * m2);
    float r0 = clip999(p0 * (m1 * m2) * inv);
    float r1 = clip999(p1 * (m0 * m2) * inv);
    float r2 = clip999(p2 * (m0 * m1) * inv);
    float np0 = 1.0f + r0, nm0 = 1.0f - r0;
    float np1 = 1.0f + r1, nm1 = 1.0f - r1;
    float np2 = 1.0f + r2, nm2 = 1.0f - r2;
    float e0 = el * np0;
    float A0 = el * (np1 * np2), A1 = e0 * np2, A2 = e0 * np1;
    float B0 = nm1 * nm2,        B1 = nm0 * nm2, B2 = nm0 * nm1;
    o0 = msg_floor(__fdividef(A0 - B0, A0 + B0));
    o1 = msg_floor(__fdividef(A1 - B1, A1 + B1));
    o2 = msg_floor(__fdividef(A2 - B2, A2 + B2));
}

// Final decision, one lane: bit = (e^{vtot} < 1) <=> el*Prod(np) < Prod(nm)
__device__ __forceinline__ float var_decide(float m0, float m1, float m2,
                                            float p0, float p1, float p2,
                                            float el) {
    float inv = __fdividef(1.0f, m0 * m1 * m2);
    float r0 = clip999(p0 * (m1 * m2) * inv);
    float r1 = clip999(p1 * (m0 * m2) * inv);
    float r2 = clip999(p2 * (m0 * m1) * inv);
    float U = el * ((1.0f + r0) * (1.0f + r1)) * (1.0f + r2);
    float D = ((1.0f - r0) * (1.0f - r1)) * (1.0f - r2);
    return (U < D) ? 1.0f : 0.0f;
}

// ---------------------------------------------------------------------------
// Fused encode + LMMSE. Block 0 additionally builds the check-node CSR
// (consumed only by the decode kernel) — hidden inside the wave structure.
// Parity via shared atomicXor over the raw cn edge list.
// ---------------------------------------------------------------------------
__global__ __launch_bounds__(256)
void enc_lmmse_kernel(const int* __restrict__ bin,
                      const int* __restrict__ cn,
                      const float4* __restrict__ hre4, const float4* __restrict__ him4,
                      const float4* __restrict__ nre4, const float4* __restrict__ nim4,
                      const float* __restrict__ ebno,
                      float* __restrict__ out_bf)
{
    __shared__ char scratch[12032];
    unsigned char* bits = (unsigned char*)scratch;      // [NUE_*N_] = 4000
    int* sp = (int*)(scratch + 4000);                   // [NUE_*M_] = 8000

    const int b = blockIdx.x;
    const int t = threadIdx.x;
    const int lane = t & 31, wid = t >> 5;

    // ---- block 0 only: build global CSR (aliases scratch; before bits) ----
    if (b == 0) {
        int*   cnt  = (int*)scratch;            // [M_]   2000
        int*   base = (int*)(scratch + 2000);   // [M_]   2000
        int*   wsum = (int*)(scratch + 4000);   // [8]      32
        short* sel  = (short*)(scratch + 4032); // [NINFOE_] 3000

        for (int m = t; m < M_; m += 256) cnt[m] = 0;
        __syncthreads();
        for (int e = t; e < NINFOE_; e += 256) atomicAdd(&cnt[cn[e]], 1);
        __syncthreads();
        int v0 = (2 * t     < M_) ? cnt[2 * t]     : 0;
        int v1 = (2 * t + 1 < M_) ? cnt[2 * t + 1] : 0;
        int s = v0 + v1, x = s;
#pragma unroll
        for (int d = 1; d < 32; d <<= 1) {
            int nn = __shfl_up_sync(0xffffffffu, x, d);
            if (lane >= d) x += nn;
        }
        if (lane == 31) wsum[wid] = x;
        __syncthreads();
        if (wid == 0) {
            int s2 = (lane < 8) ? wsum[lane] : 0;
#pragma unroll
            for (int d = 1; d < 8; d <<= 1) {
                int nn = __shfl_up_sync(0xffffffffu, s2, d);
                if (lane >= d) s2 += nn;
            }
            if (lane < 8) wsum[lane] = s2;
        }
        __syncthreads();
        int ex = x + ((wid > 0) ? wsum[wid - 1] : 0) - s;
        if (2 * t     < M_) { base[2 * t]     = ex;      g_eoff[2 * t]     = (short)ex; }
        if (2 * t + 1 < M_) { base[2 * t + 1] = ex + v0; g_eoff[2 * t + 1] = (short)(ex + v0); }
        if (t == 0) g_eoff[M_] = (short)NINFOE_;
        __syncthreads();
        for (int m = t; m < M_; m += 256) cnt[m] = 0;
        __syncthreads();
        for (int e = t; e < NINFOE_; e += 256) {
            int c = cn[e];
            int sl = atomicAdd(&cnt[c], 1);
            sel[base[c] + sl] = (short)e;
        }
        __syncthreads();
        for (int m = t; m < M_; m += 256) {
            int o0 = base[m], o1 = o0 + cnt[m];
            for (int i = o0 + 1; i < o1; i++) {
                short vv = sel[i];
                int j = i - 1;
                while (j >= o0 && sel[j] > vv) { sel[j + 1] = sel[j]; j--; }
                sel[j + 1] = vv;
            }
        }
        __syncthreads();
        for (int e = t; e < NINFOE_; e += 256) g_elist[e] = sel[e];
        __syncthreads();
    }

    // ---- stage info bits, emit bf output, zero parity accumulators ----
    const int* bb = bin + (size_t)b * NUE_ * K_;
    float* of = out_bf + (size_t)b * NUE_ * K_;
    for (int i = t; i < NUE_ * K_; i += 256) {
        int ue = i / K_, n = i - ue * K_;
        int bit = bb[i];
        bits[ue * N_ + n] = (unsigned char)bit;
        of[i] = (float)bit;
    }
    for (int i = t; i < NUE_ * M_; i += 256) sp[i] = 0;
    __syncthreads();

    // ---- parity via atomicXor over info edges (vn[e] = e/3 analytically) ----
    for (int e = t; e < NINFOE_; e += 256) {
        int c = cn[e], v = e / 3;
#pragma unroll
        for (int ue = 0; ue < 4; ue++)
            if (bits[ue * N_ + v]) atomicXor(&sp[ue * M_ + c], 1);
    }
    __syncthreads();
    for (int i = t; i < NUE_ * M_; i += 256) {
        int ue = i / M_, m = i - ue * M_;
        bits[ue * N_ + K_ + m] = (unsigned char)sp[i];
    }
    __syncthreads();

    if (t >= NSYM_) return;

    const float no  = 1.0f / (exp10f(ebno[0] * 0.1f) * 2.0f);
    const int r = b * NSYM_ + t;
    const float is2 = 0.70710678118654752440f;
    const float s10 = 0.31622776601683794f;

    float hr[4][4], hi[4][4];
#pragma unroll
    for (int i = 0; i < 4; i++) {
        float4 vr = hre4[r * 4 + i];
        float4 vi = him4[r * 4 + i];
        hr[i][0] = vr.x * is2; hr[i][1] = vr.y * is2; hr[i][2] = vr.z * is2; hr[i][3] = vr.w * is2;
        hi[i][0] = vi.x * is2; hi[i][1] = vi.y * is2; hi[i][2] = vi.z * is2; hi[i][3] = vi.w * is2;
    }

    float xr[4], xi[4];
#pragma unroll
    for (int j = 0; j < 4; j++) {
        uchar4 cb = *(const uchar4*)&bits[j * N_ + 4 * t];
        xr[j] = (float)((1 - 2 * (int)cb.x) * (1 + 2 * (int)cb.z)) * s10;
        xi[j] = (float)((1 - 2 * (int)cb.y) * (1 + 2 * (int)cb.w)) * s10;
    }

    const float ns = sqrtf(no * 0.5f);
    float4 wr4 = nre4[r], wi4 = nim4[r];
    float yr[4] = {wr4.x * ns, wr4.y * ns, wr4.z * ns, wr4.w * ns};
    float yi[4] = {wi4.x * ns, wi4.y * ns, wi4.z * ns, wi4.w * ns};
#pragma unroll
    for (int i = 0; i < 4; i++)
#pragma unroll
        for (int j = 0; j < 4; j++) {
            yr[i] += hr[i][j] * xr[j] - hi[i][j] * xi[j];
            yi[i] += hr[i][j] * xi[j] + hi[i][j] * xr[j];
        }

    float rr[4], ri[4];
#pragma unroll
    for (int j = 0; j < 4; j++) {
        float ar = 0.f, ai = 0.f;
#pragma unroll
        for (int i = 0; i < 4; i++) {
            ar += hr[i][j] * yr[i] + hi[i][j] * yi[i];
            ai += hr[i][j] * yi[i] - hi[i][j] * yr[i];
        }
        rr[j] = ar; ri[j] = ai;
    }

    float Br[4][4], Bi[4][4];
#pragma unroll
    for (int j = 0; j < 4; j++)
#pragma unroll
        for (int k = 0; k < 4; k++) {
            if (k > j) continue;
            float ar = (j == k) ? no : 0.f;
            float ai = 0.f;
#pragma unroll
            for (int i = 0; i < 4; i++) {
                ar += hr[i][j] * hr[i][k] + hi[i][j] * hi[i][k];
                ai += hr[i][j] * hi[i][k] - hi[i][j] * hr[i][k];
            }
            Br[j][k] = ar; Bi[j][k] = ai;
        }

    float rk[4];
#pragma unroll
    for (int k = 0; k < 4; k++) {
        float v = Br[k][k];
#pragma unroll
        for (int j = 0; j < 4; j++)
            if (j < k) v -= Br[k][j] * Br[k][j] + Bi[k][j] * Bi[k][j];
        float inv = rsqrtf(v);
        rk[k] = inv;
#pragma unroll
        for (int i = 0; i < 4; i++) {
            if (i <= k) continue;
            float cr = Br[i][k], ci = Bi[i][k];
#pragma unroll
            for (int j = 0; j < 4; j++)
                if (j < k) {
                    cr -= Br[i][j] * Br[k][j] + Bi[i][j] * Bi[k][j];
                    ci -= Bi[i][j] * Br[k][j] - Br[i][j] * Bi[k][j];
                }
            Br[i][k] = cr * inv; Bi[i][k] = ci * inv;
        }
    }

    float vr_[4], vi_[4];
#pragma unroll
    for (int i = 0; i < 4; i++) {
        float ar = rr[i], ai = ri[i];
#pragma unroll
        for (int j = 0; j < 4; j++)
            if (j < i) {
                ar -= Br[i][j] * vr_[j] - Bi[i][j] * vi_[j];
                ai -= Br[i][j] * vi_[j] + Bi[i][j] * vr_[j];
            }
        vr_[i] = ar * rk[i]; vi_[i] = ai * rk[i];
    }
    float xrw[4], xiw[4];
#pragma unroll
    for (int ii = 0; ii < 4; ii++) {
        int i = 3 - ii;
        float ar = vr_[i], ai = vi_[i];
#pragma unroll
        for (int j = 0; j < 4; j++)
            if (j > i) {
                ar -= Br[j][i] * xrw[j] + Bi[j][i] * xiw[j];
                ai -= Br[j][i] * xiw[j] - Bi[j][i] * xrw[j];
            }
        xrw[i] = ar * rk[i]; xiw[i] = ai * rk[i];
    }

    float dj[4];
#pragma unroll
    for (int j = 0; j < 4; j++) {
        float wr[4], wi[4];
#pragma unroll
        for (int i = 0; i < 4; i++) { wr[i] = 0.f; wi[i] = 0.f; }
        wr[j] = rk[j];
        float acc = rk[j] * rk[j];
#pragma unroll
        for (int i = 0; i < 4; i++) {
            if (i <= j) continue;
            float sr = 0.f, si = 0.f;
#pragma unroll
            for (int q = 0; q < 4; q++)
                if (q >= j && q < i) {
                    sr += Br[i][q] * wr[q] - Bi[i][q] * wi[q];
                    si += Br[i][q] * wi[q] + Bi[i][q] * wr[q];
                }
            wr[i] = -sr * rk[i]; wi[i] = -si * rk[i];
            acc += wr[i] * wr[i] + wi[i] * wi[i];
        }
        dj[j] = acc;
    }

#pragma unroll
    for (int c = 0; c < 4; c++) {
        float d = 1.0f - no * dj[c];
        float invd = 1.0f / d;
        float xhr = xrw[c] * invd, xhi = xiw[c] * invd;
        float noeff = fmaxf(invd - 1.0f, 1e-12f);
        float inoe = 1.0f / noeff;

        float a1  = xhr - s10,  a3  = xhr - 3.f * s10;
        float am1 = xhr + s10,  am3 = xhr + 3.f * s10;
        float f1 = -(a1 * a1), f3 = -(a3 * a3), fm1 = -(am1 * am1), fm3 = -(am3 * am3);
        float g1_ = xhi - s10,  g3_ = xhi - 3.f * s10;
        float gm1_ = xhi + s10, gm3_ = xhi + 3.f * s10;
        float g1 = -(g1_ * g1_), g3 = -(g3_ * g3_), gm1 = -(gm1_ * gm1_), gm3 = -(gm3_ * gm3_);

        float4 out = make_float4((fmaxf(f1, f3)  - fmaxf(fm1, fm3)) * inoe,
                                 (fmaxf(g1, g3)  - fmaxf(gm1, gm3)) * inoe,
                                 (fmaxf(f1, fm1) - fmaxf(f3, fm3))  * inoe,
                                 (fmaxf(g1, gm1) - fmaxf(g3, gm3))  * inoe);
        *(float4*)&g_llr[(size_t)(b * NUE_ + c) * N_ + 4 * t] = out;
    }
}

// ---------------------------------------------------------------------------
// Decoder: one block per batch element, 4 codewords as float4 lanes, 512 thr.
// Identity check mapping (coalesced sP/sTp — R11's permutation regressed).
// Variable phase: 4 MUFU per lane (1 reciprocal + 3 message divs),
// exponential-domain messages; final decision div-free.
// ---------------------------------------------------------------------------
extern __shared__ unsigned char dynsmem[];
#define DEC_SMEM (24000 + 8000 + 8000 + 8000 + 3000)

__global__ __launch_bounds__(512, 4)
void decode_kernel(const int* __restrict__ cn, float* __restrict__ out_bhat) {
    float4* sT  = (float4*)dynsmem;          // [NINFOE_] v->c message tanh
    float4* sP  = sT + NINFOE_;              // [M_]  check products
    float4* sTp = sP + M_;                   // [M_]  parity-edge tanh (invariant)
    float4* sEL = sTp + M_;                  // [K_]  clamped exp(Lch)
    short* selist = (short*)(sEL + K_);      // [NINFOE_]

    const int b = blockIdx.x;
    const int t = threadIdx.x;
    const float* Lb = g_llr + (size_t)b * NUE_ * N_;

    for (int e = t; e < NINFOE_; e += 512) selist[e] = g_elist[e];

    int c0 = 0, c1 = 0, c2 = 0, co0 = 0, co1 = 0;
    if (t < K_) {
        float4 l;
        l.x = Lb[0 * N_ + t]; l.y = Lb[1 * N_ + t];
        l.z = Lb[2 * N_ + t]; l.w = Lb[3 * N_ + t];
        float4 el;
        el.x = fminf(__expf(l.x), 1e30f); el.y = fminf(__expf(l.y), 1e30f);
        el.z = fminf(__expf(l.z), 1e30f); el.w = fminf(__expf(l.w), 1e30f);
        sEL[t] = el;
        c0 = cn[3 * t]; c1 = cn[3 * t + 1]; c2 = cn[3 * t + 2];
        float4 m;
        m.x = tanh_clip_half(l.x * 0.5f);
        m.y = tanh_clip_half(l.y * 0.5f);
        m.z = tanh_clip_half(l.z * 0.5f);
        m.w = tanh_clip_half(l.w * 0.5f);
        sT[3 * t] = m; sT[3 * t + 1] = m; sT[3 * t + 2] = m;
    }
    if (t < M_) {
        float4 lp;
        lp.x = Lb[0 * N_ + K_ + t]; lp.y = Lb[1 * N_ + K_ + t];
        lp.z = Lb[2 * N_ + K_ + t]; lp.w = Lb[3 * N_ + K_ + t];
        float4 tp;
        tp.x = tanh_clip_half(lp.x * 0.5f);
        tp.y = tanh_clip_half(lp.y * 0.5f);
        tp.z = tanh_clip_half(lp.z * 0.5f);
        tp.w = tanh_clip_half(lp.w * 0.5f);
        sTp[t] = tp;
        co0 = g_eoff[t]; co1 = g_eoff[t + 1];
    }
    __syncthreads();

    float* oh = out_bhat + (size_t)b * NUE_ * K_;

    for (int it = 0; it < NITER_; it++) {
        // check phase: product over info edges * parity tanh -> sP[t]
        if (t < M_) {
            float4 p = sTp[t];
            for (int q = co0; q < co1; q++) {
                float4 tt = sT[selist[q]];
                p.x *= tt.x; p.y *= tt.y; p.z *= tt.z; p.w *= tt.w;
            }
            sP[t] = p;
        }
        __syncthreads();
        // variable phase
        if (t < K_) {
            float4 m0 = sT[3 * t], m1 = sT[3 * t + 1], m2 = sT[3 * t + 2];
            float4 p0 = sP[c0], p1 = sP[c1], p2 = sP[c2];
            float4 el = sEL[t];
            if (it < NITER_ - 1) {
                float4 o0, o1, o2;
                var_update(m0.x, m1.x, m2.x, p0.x, p1.x, p2.x, el.x, o0.x, o1.x, o2.x);
                var_update(m0.y, m1.y, m2.y, p0.y, p1.y, p2.y, el.y, o0.y, o1.y, o2.y);
                var_update(m0.z, m1.z, m2.z, p0.z, p1.z, p2.z, el.z, o0.z, o1.z, o2.z);
                var_update(m0.w, m1.w, m2.w, p0.w, p1.w, p2.w, el.w, o0.w, o1.w, o2.w);
                sT[3 * t] = o0; sT[3 * t + 1] = o1; sT[3 * t + 2] = o2;
            } else {
                oh[0 * K_ + t] = var_decide(m0.x, m1.x, m2.x, p0.x, p1.x, p2.x, el.x);
                oh[1 * K_ + t] = var_decide(m0.y, m1.y, m2.y, p0.y, p1.y, p2.y, el.y);
                oh[2 * K_ + t] = var_decide(m0.z, m1.z, m2.z, p0.z, p1.z, p2.z, el.z);
                oh[3 * K_ + t] = var_decide(m0.w, m1.w, m2.w, p0.w, p1.w, p2.w, el.w);
            }
        }
        if (it < NITER_ - 1) __syncthreads();
    }
}

// ---------------------------------------------------------------------------
extern "C" void kernel_launch(void* const* d_in, const int* in_sizes, int n_in,
                              void* d_out, int out_size) {
    int shift = 10 - n_in;
    const float* ebno = (const float*)d_in[1 - shift];
    const int*   b    = (const int*)  d_in[2 - shift];
    const int*   cn   = (const int*)  d_in[4 - shift];
    const float* h_re = (const float*)d_in[6 - shift];
    const float* h_im = (const float*)d_in[7 - shift];
    const float* n_re = (const float*)d_in[8 - shift];
    const float* n_im = (const float*)d_in[9 - shift];

    float* out_bf = (float*)d_out;                       // (batch, NUE, K)
    float* out_bh = (float*)d_out + BATCH * NUE_ * K_;   // (batch, NUE, K)

    cudaFuncSetAttribute(decode_kernel, cudaFuncAttributeMaxDynamicSharedMemorySize, DEC_SMEM);

    enc_lmmse_kernel<<<BATCH, 256>>>(b, cn,
                                     (const float4*)h_re, (const float4*)h_im,
                                     (const float4*)n_re, (const float4*)n_im,
                                     ebno, out_bf);
    decode_kernel<<<BATCH, 512, DEC_SMEM>>>(cn, out_bh);
}

// round 13
// speedup vs baseline: 1.1143x; 1.1108x over previous
#include <cuda_runtime.h>

// Problem constants (fixed by reference)
#define BATCH   1000
#define NUE_    4
#define K_      500
#define M_      500
#define N_      1000
#define NSYM_   250
#define NEDGE_  2000
#define NINFOE_ 1500
#define NITER_  5

// Static scratch
__device__ float g_llr[BATCH * NUE_ * N_];   // channel LLRs
__device__ short g_eoff[M_ + 1];
__device__ short g_elist[NINFOE_];

// ---------------------------------------------------------------------------
// Hybrid tanh (validated R3-R12) — init only.
// ---------------------------------------------------------------------------
__device__ __forceinline__ float tanh_clip_half(float x) {
    x = fminf(fmaxf(x, -9.9f), 9.9f);
    float ax = fabsf(x);
    float x2 = x * x;
    float num = x * fmaf(x2, fmaf(x2, 1.0f, 105.0f), 945.0f);
    float den = fmaf(x2, fmaf(x2, 15.0f, 420.0f), 945.0f);
    float tp  = __fdividef(num, den);
    float e   = __expf(2.0f * ax);
    float te  = copysignf(1.0f - __fdividef(2.0f, e + 1.0f), x);
    float t   = (ax < 1.0f) ? tp : te;
    return (t >= 0.f) ? fmaxf(t, 1e-7f) : fminf(t, -1e-7f);
}

__device__ __forceinline__ float clip999(float x) {
    return fminf(fmaxf(x, -0.999999f), 0.999999f);
}

__device__ __forceinline__ float msg_floor(float t) {
    return (t >= 0.f) ? fmaxf(t, 1e-7f) : fminf(t, -1e-7f);
}

// Variable update, one lane (validated R11/R12: rel_err 0.0).
// rho_i = clip(p_i/m_i) via one reciprocal; message_i = (A_i-B_i)/(A_i+B_i),
// A_i = el*np_j*np_k, B_i = nm_j*nm_k  (exponential-domain tanh identity).
__device__ __forceinline__ void var_update(float m0, float m1, float m2,
                                           float p0, float p1, float p2,
                                           float el,
                                           float& o0, float& o1, float& o2) {
    float inv = __fdividef(1.0f, m0 * m1 * m2);
    float r0 = clip999(p0 * (m1 * m2) * inv);
    float r1 = clip999(p1 * (m0 * m2) * inv);
    float r2 = clip999(p2 * (m0 * m1) * inv);
    float np0 = 1.0f + r0, nm0 = 1.0f - r0;
    float np1 = 1.0f + r1, nm1 = 1.0f - r1;
    float np2 = 1.0f + r2, nm2 = 1.0f - r2;
    float e0 = el * np0;
    float A0 = el * (np1 * np2), A1 = e0 * np2, A2 = e0 * np1;
    float B0 = nm1 * nm2,        B1 = nm0 * nm2, B2 = nm0 * nm1;
    o0 = msg_floor(__fdividef(A0 - B0, A0 + B0));
    o1 = msg_floor(__fdividef(A1 - B1, A1 + B1));
    o2 = msg_floor(__fdividef(A2 - B2, A2 + B2));
}

// Final decision, one lane: bit = (e^{vtot} < 1) <=> el*Prod(np) < Prod(nm)
__device__ __forceinline__ float var_decide(float m0, float m1, float m2,
                                            float p0, float p1, float p2,
                                            float el) {
    float inv = __fdividef(1.0f, m0 * m1 * m2);
    float r0 = clip999(p0 * (m1 * m2) * inv);
    float r1 = clip999(p1 * (m0 * m2) * inv);
    float r2 = clip999(p2 * (m0 * m1) * inv);
    float U = el * ((1.0f + r0) * (1.0f + r1)) * (1.0f + r2);
    float D = ((1.0f - r0) * (1.0f - r1)) * (1.0f - r2);
    return (U < D) ? 1.0f : 0.0f;
}

// ---------------------------------------------------------------------------
// Fused encode + LMMSE. Block 0 additionally builds the check-node CSR
// (consumed only by the decode kernel) — hidden inside the wave structure.
// Parity via shared atomicXor over the raw cn edge list.
// ---------------------------------------------------------------------------
__global__ __launch_bounds__(256)
void enc_lmmse_kernel(const int* __restrict__ bin,
                      const int* __restrict__ cn,
                      const float4* __restrict__ hre4, const float4* __restrict__ him4,
                      const float4* __restrict__ nre4, const float4* __restrict__ nim4,
                      const float* __restrict__ ebno,
                      float* __restrict__ out_bf)
{
    __shared__ char scratch[12032];
    unsigned char* bits = (unsigned char*)scratch;      // [NUE_*N_] = 4000
    int* sp = (int*)(scratch + 4000);                   // [NUE_*M_] = 8000

    const int b = blockIdx.x;
    const int t = threadIdx.x;
    const int lane = t & 31, wid = t >> 5;

    // ---- block 0 only: build global CSR (aliases scratch; before bits) ----
    if (b == 0) {
        int*   cnt  = (int*)scratch;            // [M_]   2000
        int*   base = (int*)(scratch + 2000);   // [M_]   2000
        int*   wsum = (int*)(scratch + 4000);   // [8]      32
        short* sel  = (short*)(scratch + 4032); // [NINFOE_] 3000

        for (int m = t; m < M_; m += 256) cnt[m] = 0;
        __syncthreads();
        for (int e = t; e < NINFOE_; e += 256) atomicAdd(&cnt[cn[e]], 1);
        __syncthreads();
        int v0 = (2 * t     < M_) ? cnt[2 * t]     : 0;
        int v1 = (2 * t + 1 < M_) ? cnt[2 * t + 1] : 0;
        int s = v0 + v1, x = s;
#pragma unroll
        for (int d = 1; d < 32; d <<= 1) {
            int nn = __shfl_up_sync(0xffffffffu, x, d);
            if (lane >= d) x += nn;
        }
        if (lane == 31) wsum[wid] = x;
        __syncthreads();
        if (wid == 0) {
            int s2 = (lane < 8) ? wsum[lane] : 0;
#pragma unroll
            for (int d = 1; d < 8; d <<= 1) {
                int nn = __shfl_up_sync(0xffffffffu, s2, d);
                if (lane >= d) s2 += nn;
            }
            if (lane < 8) wsum[lane] = s2;
        }
        __syncthreads();
        int ex = x + ((wid > 0) ? wsum[wid - 1] : 0) - s;
        if (2 * t     < M_) { base[2 * t]     = ex;      g_eoff[2 * t]     = (short)ex; }
        if (2 * t + 1 < M_) { base[2 * t + 1] = ex + v0; g_eoff[2 * t + 1] = (short)(ex + v0); }
        if (t == 0) g_eoff[M_] = (short)NINFOE_;
        __syncthreads();
        for (int m = t; m < M_; m += 256) cnt[m] = 0;
        __syncthreads();
        for (int e = t; e < NINFOE_; e += 256) {
            int c = cn[e];
            int sl = atomicAdd(&cnt[c], 1);
            sel[base[c] + sl] = (short)e;
        }
        __syncthreads();
        for (int m = t; m < M_; m += 256) {
            int o0 = base[m], o1 = o0 + cnt[m];
            for (int i = o0 + 1; i < o1; i++) {
                short vv = sel[i];
                int j = i - 1;
                while (j >= o0 && sel[j] > vv) { sel[j + 1] = sel[j]; j--; }
                sel[j + 1] = vv;
            }
        }
        __syncthreads();
        for (int e = t; e < NINFOE_; e += 256) g_elist[e] = sel[e];
        __syncthreads();
    }

    // ---- stage info bits, emit bf output, zero parity accumulators ----
    const int* bb = bin + (size_t)b * NUE_ * K_;
    float* of = out_bf + (size_t)b * NUE_ * K_;
    for (int i = t; i < NUE_ * K_; i += 256) {
        int ue = i / K_, n = i - ue * K_;
        int bit = bb[i];
        bits[ue * N_ + n] = (unsigned char)bit;
        of[i] = (float)bit;
    }
    for (int i = t; i < NUE_ * M_; i += 256) sp[i] = 0;
    __syncthreads();

    // ---- parity via atomicXor over info edges (vn[e] = e/3 analytically) ----
    for (int e = t; e < NINFOE_; e += 256) {
        int c = cn[e], v = e / 3;
#pragma unroll
        for (int ue = 0; ue < 4; ue++)
            if (bits[ue * N_ + v]) atomicXor(&sp[ue * M_ + c], 1);
    }
    __syncthreads();
    for (int i = t; i < NUE_ * M_; i += 256) {
        int ue = i / M_, m = i - ue * M_;
        bits[ue * N_ + K_ + m] = (unsigned char)sp[i];
    }
    __syncthreads();

    if (t >= NSYM_) return;

    const float no  = 1.0f / (exp10f(ebno[0] * 0.1f) * 2.0f);
    const int r = b * NSYM_ + t;
    const float is2 = 0.70710678118654752440f;
    const float s10 = 0.31622776601683794f;

    float hr[4][4], hi[4][4];
#pragma unroll
    for (int i = 0; i < 4; i++) {
        float4 vr = hre4[r * 4 + i];
        float4 vi = him4[r * 4 + i];
        hr[i][0] = vr.x * is2; hr[i][1] = vr.y * is2; hr[i][2] = vr.z * is2; hr[i][3] = vr.w * is2;
        hi[i][0] = vi.x * is2; hi[i][1] = vi.y * is2; hi[i][2] = vi.z * is2; hi[i][3] = vi.w * is2;
    }

    float xr[4], xi[4];
#pragma unroll
    for (int j = 0; j < 4; j++) {
        uchar4 cb = *(const uchar4*)&bits[j * N_ + 4 * t];
        xr[j] = (float)((1 - 2 * (int)cb.x) * (1 + 2 * (int)cb.z)) * s10;
        xi[j] = (float)((1 - 2 * (int)cb.y) * (1 + 2 * (int)cb.w)) * s10;
    }

    const float ns = sqrtf(no * 0.5f);
    float4 wr4 = nre4[r], wi4 = nim4[r];
    float yr[4] = {wr4.x * ns, wr4.y * ns, wr4.z * ns, wr4.w * ns};
    float yi[4] = {wi4.x * ns, wi4.y * ns, wi4.z * ns, wi4.w * ns};
#pragma unroll
    for (int i = 0; i < 4; i++)
#pragma unroll
        for (int j = 0; j < 4; j++) {
            yr[i] += hr[i][j] * xr[j] - hi[i][j] * xi[j];
            yi[i] += hr[i][j] * xi[j] + hi[i][j] * xr[j];
        }

    float rr[4], ri[4];
#pragma unroll
    for (int j = 0; j < 4; j++) {
        float ar = 0.f, ai = 0.f;
#pragma unroll
        for (int i = 0; i < 4; i++) {
            ar += hr[i][j] * yr[i] + hi[i][j] * yi[i];
            ai += hr[i][j] * yi[i] - hi[i][j] * yr[i];
        }
        rr[j] = ar; ri[j] = ai;
    }

    float Br[4][4], Bi[4][4];
#pragma unroll
    for (int j = 0; j < 4; j++)
#pragma unroll
        for (int k = 0; k < 4; k++) {
            if (k > j) continue;
            float ar = (j == k) ? no : 0.f;
            float ai = 0.f;
#pragma unroll
            for (int i = 0; i < 4; i++) {
                ar += hr[i][j] * hr[i][k] + hi[i][j] * hi[i][k];
                ai += hr[i][j] * hi[i][k] - hi[i][j] * hr[i][k];
            }
            Br[j][k] = ar; Bi[j][k] = ai;
        }

    float rk[4];
#pragma unroll
    for (int k = 0; k < 4; k++) {
        float v = Br[k][k];
#pragma unroll
        for (int j = 0; j < 4; j++)
            if (j < k) v -= Br[k][j] * Br[k][j] + Bi[k][j] * Bi[k][j];
        float inv = rsqrtf(v);
        rk[k] = inv;
#pragma unroll
        for (int i = 0; i < 4; i++) {
            if (i <= k) continue;
            float cr = Br[i][k], ci = Bi[i][k];
#pragma unroll
            for (int j = 0; j < 4; j++)
                if (j < k) {
                    cr -= Br[i][j] * Br[k][j] + Bi[i][j] * Bi[k][j];
                    ci -= Bi[i][j] * Br[k][j] - Br[i][j] * Bi[k][j];
                }
            Br[i][k] = cr * inv; Bi[i][k] = ci * inv;
        }
    }

    float vr_[4], vi_[4];
#pragma unroll
    for (int i = 0; i < 4; i++) {
        float ar = rr[i], ai = ri[i];
#pragma unroll
        for (int j = 0; j < 4; j++)
            if (j < i) {
                ar -= Br[i][j] * vr_[j] - Bi[i][j] * vi_[j];
                ai -= Br[i][j] * vi_[j] + Bi[i][j] * vr_[j];
            }
        vr_[i] = ar * rk[i]; vi_[i] = ai * rk[i];
    }
    float xrw[4], xiw[4];
#pragma unroll
    for (int ii = 0; ii < 4; ii++) {
        int i = 3 - ii;
        float ar = vr_[i], ai = vi_[i];
#pragma unroll
        for (int j = 0; j < 4; j++)
            if (j > i) {
                ar -= Br[j][i] * xrw[j] + Bi[j][i] * xiw[j];
                ai -= Br[j][i] * xiw[j] - Bi[j][i] * xrw[j];
            }
        xrw[i] = ar * rk[i]; xiw[i] = ai * rk[i];
    }

    float dj[4];
#pragma unroll
    for (int j = 0; j < 4; j++) {
        float wr[4], wi[4];
#pragma unroll
        for (int i = 0; i < 4; i++) { wr[i] = 0.f; wi[i] = 0.f; }
        wr[j] = rk[j];
        float acc = rk[j] * rk[j];
#pragma unroll
        for (int i = 0; i < 4; i++) {
            if (i <= j) continue;
            float sr = 0.f, si = 0.f;
#pragma unroll
            for (int q = 0; q < 4; q++)
                if (q >= j && q < i) {
                    sr += Br[i][q] * wr[q] - Bi[i][q] * wi[q];
                    si += Br[i][q] * wi[q] + Bi[i][q] * wr[q];
                }
            wr[i] = -sr * rk[i]; wi[i] = -si * rk[i];
            acc += wr[i] * wr[i] + wi[i] * wi[i];
        }
        dj[j] = acc;
    }

#pragma unroll
    for (int c = 0; c < 4; c++) {
        float d = 1.0f - no * dj[c];
        float invd = 1.0f / d;
        float xhr = xrw[c] * invd, xhi = xiw[c] * invd;
        float noeff = fmaxf(invd - 1.0f, 1e-12f);
        float inoe = 1.0f / noeff;

        float a1  = xhr - s10,  a3  = xhr - 3.f * s10;
        float am1 = xhr + s10,  am3 = xhr + 3.f * s10;
        float f1 = -(a1 * a1), f3 = -(a3 * a3), fm1 = -(am1 * am1), fm3 = -(am3 * am3);
        float g1_ = xhi - s10,  g3_ = xhi - 3.f * s10;
        float gm1_ = xhi + s10, gm3_ = xhi + 3.f * s10;
        float g1 = -(g1_ * g1_), g3 = -(g3_ * g3_), gm1 = -(gm1_ * gm1_), gm3 = -(gm3_ * gm3_);

        float4 out = make_float4((fmaxf(f1, f3)  - fmaxf(fm1, fm3)) * inoe,
                                 (fmaxf(g1, g3)  - fmaxf(gm1, gm3)) * inoe,
                                 (fmaxf(f1, fm1) - fmaxf(f3, fm3))  * inoe,
                                 (fmaxf(g1, gm1) - fmaxf(g3, gm3))  * inoe);
        *(float4*)&g_llr[(size_t)(b * NUE_ + c) * N_ + 4 * t] = out;
    }
}

// ---------------------------------------------------------------------------
// Decoder: one block per batch element, 4 codewords as float4 lanes, 512 thr.
// __launch_bounds__(512, 3): reg budget 42 (was 32 at 4 blocks) — the R11/R12
// variable phase spilled to local under the 32-reg cap (L2 4%->13.5%, issue
// 70->57); trade 64->48 resident warps for spill-free execution.
// ---------------------------------------------------------------------------
extern __shared__ unsigned char dynsmem[];
#define DEC_SMEM (24000 + 8000 + 8000 + 8000 + 3000)

__global__ __launch_bounds__(512, 3)
void decode_kernel(const int* __restrict__ cn, float* __restrict__ out_bhat) {
    float4* sT  = (float4*)dynsmem;          // [NINFOE_] v->c message tanh
    float4* sP  = sT + NINFOE_;              // [M_]  check products
    float4* sTp = sP + M_;                   // [M_]  parity-edge tanh (invariant)
    float4* sEL = sTp + M_;                  // [K_]  clamped exp(Lch)
    short* selist = (short*)(sEL + K_);      // [NINFOE_]

    const int b = blockIdx.x;
    const int t = threadIdx.x;
    const float* Lb = g_llr + (size_t)b * NUE_ * N_;

    for (int e = t; e < NINFOE_; e += 512) selist[e] = g_elist[e];

    int c0 = 0, c1 = 0, c2 = 0, co0 = 0, co1 = 0;
    if (t < K_) {
        float4 l;
        l.x = Lb[0 * N_ + t]; l.y = Lb[1 * N_ + t];
        l.z = Lb[2 * N_ + t]; l.w = Lb[3 * N_ + t];
        float4 el;
        el.x = fminf(__expf(l.x), 1e30f); el.y = fminf(__expf(l.y), 1e30f);
        el.z = fminf(__expf(l.z), 1e30f); el.w = fminf(__expf(l.w), 1e30f);
        sEL[t] = el;
        c0 = cn[3 * t]; c1 = cn[3 * t + 1]; c2 = cn[3 * t + 2];
        float4 m;
        m.x = tanh_clip_half(l.x * 0.5f);
        m.y = tanh_clip_half(l.y * 0.5f);
        m.z = tanh_clip_half(l.z * 0.5f);
        m.w = tanh_clip_half(l.w * 0.5f);
        sT[3 * t] = m; sT[3 * t + 1] = m; sT[3 * t + 2] = m;
    }
    if (t < M_) {
        float4 lp;
        lp.x = Lb[0 * N_ + K_ + t]; lp.y = Lb[1 * N_ + K_ + t];
        lp.z = Lb[2 * N_ + K_ + t]; lp.w = Lb[3 * N_ + K_ + t];
        float4 tp;
        tp.x = tanh_clip_half(lp.x * 0.5f);
        tp.y = tanh_clip_half(lp.y * 0.5f);
        tp.z = tanh_clip_half(lp.z * 0.5f);
        tp.w = tanh_clip_half(lp.w * 0.5f);
        sTp[t] = tp;
        co0 = g_eoff[t]; co1 = g_eoff[t + 1];
    }
    __syncthreads();

    float* oh = out_bhat + (size_t)b * NUE_ * K_;

    for (int it = 0; it < NITER_; it++) {
        // check phase: product over info edges * parity tanh -> sP[t]
        if (t < M_) {
            float4 p = sTp[t];
            for (int q = co0; q < co1; q++) {
                float4 tt = sT[selist[q]];
                p.x *= tt.x; p.y *= tt.y; p.z *= tt.z; p.w *= tt.w;
            }
            sP[t] = p;
        }
        __syncthreads();
        // variable phase
        if (t < K_) {
            float4 m0 = sT[3 * t], m1 = sT[3 * t + 1], m2 = sT[3 * t + 2];
            float4 p0 = sP[c0], p1 = sP[c1], p2 = sP[c2];
            float4 el = sEL[t];
            if (it < NITER_ - 1) {
                float4 o0, o1, o2;
                var_update(m0.x, m1.x, m2.x, p0.x, p1.x, p2.x, el.x, o0.x, o1.x, o2.x);
                var_update(m0.y, m1.y, m2.y, p0.y, p1.y, p2.y, el.y, o0.y, o1.y, o2.y);
                var_update(m0.z, m1.z, m2.z, p0.z, p1.z, p2.z, el.z, o0.z, o1.z, o2.z);
                var_update(m0.w, m1.w, m2.w, p0.w, p1.w, p2.w, el.w, o0.w, o1.w, o2.w);
                sT[3 * t] = o0; sT[3 * t + 1] = o1; sT[3 * t + 2] = o2;
            } else {
                oh[0 * K_ + t] = var_decide(m0.x, m1.x, m2.x, p0.x, p1.x, p2.x, el.x);
                oh[1 * K_ + t] = var_decide(m0.y, m1.y, m2.y, p0.y, p1.y, p2.y, el.y);
                oh[2 * K_ + t] = var_decide(m0.z, m1.z, m2.z, p0.z, p1.z, p2.z, el.z);
                oh[3 * K_ + t] = var_decide(m0.w, m1.w, m2.w, p0.w, p1.w, p2.w, el.w);
            }
        }
        if (it < NITER_ - 1) __syncthreads();
    }
}

// ---------------------------------------------------------------------------
extern "C" void kernel_launch(void* const* d_in, const int* in_sizes, int n_in,
                              void* d_out, int out_size) {
    int shift = 10 - n_in;
    const float* ebno = (const float*)d_in[1 - shift];
    const int*   b    = (const int*)  d_in[2 - shift];
    const int*   cn   = (const int*)  d_in[4 - shift];
    const float* h_re = (const float*)d_in[6 - shift];
    const float* h_im = (const float*)d_in[7 - shift];
    const float* n_re = (const float*)d_in[8 - shift];
    const float* n_im = (const float*)d_in[9 - shift];

    float* out_bf = (float*)d_out;                       // (batch, NUE, K)
    float* out_bh = (float*)d_out + BATCH * NUE_ * K_;   // (batch, NUE, K)

    cudaFuncSetAttribute(decode_kernel, cudaFuncAttributeMaxDynamicSharedMemorySize, DEC_SMEM);

    enc_lmmse_kernel<<<BATCH, 256>>>(b, cn,
                                     (const float4*)h_re, (const float4*)h_im,
                                     (const float4*)n_re, (const float4*)n_im,
                                     ebno, out_bf);
    decode_kernel<<<BATCH, 512, DEC_SMEM>>>(cn, out_bh);
}